// round 6
// baseline (speedup 1.0000x reference)
#include <cuda_runtime.h>
#include <cstdint>

typedef unsigned long long ull;

#define H     51
#define G4    204
#define NU    52          // padded units (51 real + 1 pad)
#define GP    208         // padded gate cols = 4*NU, interleaved col = 4u+gate
#define HROW  212         // dup-h row stride (208 used: 104 slots x 2)
#define SZ_HBUF (8*HROW)  // 1696 floats per ping-pong buffer
#define BB    8
#define TSEQ  512
#define FUT   64
#define TTOT  (TSEQ + FUT)
#define NT    416         // 13 warps: thread = (batch, unit)
#define INROW 516         // input row stride (bank-spread)

// ---- smem layout (float offsets) ----
#define OFF_W1T  0
#define SZ_W1T   (52*GP)                 // 10816
#define OFF_W2T  (OFF_W1T + SZ_W1T)
#define SZ_W2T   (104*GP)                // 21632
#define OFF_WX   (OFF_W2T + SZ_W2T)
#define OFF_B1   (OFF_WX + GP)
#define OFF_B2   (OFF_B1 + GP)
#define OFF_WL   (OFF_B2 + GP)
#define OFF_IN   (OFF_WL + 64)
#define SZ_IN    (BB*INROW)              // 4128
#define OFF_HD   (OFF_IN + SZ_IN)
#define OFF_OUT  (OFF_HD + 2*SZ_HBUF)
#define OFF_BL   (OFF_OUT + 8)
#define SMEM_FLOATS (OFF_BL + 4)         // ~40668 -> ~162.7 KB
#define SMEM_BYTES  (SMEM_FLOATS * 4)

__device__ __forceinline__ ull ffma2(ull a, ull b, ull c) {
    ull d;
    asm("fma.rn.f32x2 %0, %1, %2, %3;" : "=l"(d) : "l"(a), "l"(b), "l"(c));
    return d;
}

__device__ __forceinline__ ull dup2(float v) {
    ull r;
    unsigned u = __float_as_uint(v);
    asm("mov.b64 %0, {%1, %2};" : "=l"(r) : "r"(u), "r"(u));
    return r;
}

__device__ __forceinline__ float fsig(float x) {
    float e = __expf(-x);
    return __fdividef(1.0f, 1.0f + e);
}

__device__ __forceinline__ float ftanh_acc(float x) {
    float a = fabsf(x);
    float e = __expf(-2.0f * a);           // <= 1, no overflow
    float r = __fdividef(1.0f - e, 1.0f + e);
    return copysignf(r, x);
}

// Full-K partial: thread accumulates its unit's 4 gate cols over NP k-pairs.
// Per pair: 2 weight LDS.128 (broadcast over 8 batch lanes) + 1 dup-h LDS.128
// (8 distinct banks) + 4 FFMA2. Accumulators stay in registers end-to-end.
template<int NP>
__device__ __forceinline__ void mv(const float* __restrict__ WT,
                                   const float* __restrict__ hb,
                                   ull& a0, ull& a1, int j0)
{
    #pragma unroll
    for (int kp = 0; kp < NP; ++kp) {
        ulonglong2 w0 = *reinterpret_cast<const ulonglong2*>(WT + (2*kp  )*GP + j0);
        ulonglong2 w1 = *reinterpret_cast<const ulonglong2*>(WT + (2*kp+1)*GP + j0);
        ulonglong2 hv = *reinterpret_cast<const ulonglong2*>(hb + 4*kp);
        a0 = ffma2(w0.x, hv.x, a0);
        a1 = ffma2(w0.y, hv.x, a1);
        a0 = ffma2(w1.x, hv.y, a0);
        a1 = ffma2(w1.y, hv.y, a1);
    }
}

// In-register LSTM cell update: a0 = (i,f), a1 = (g,o); writes dup h.
__device__ __forceinline__ void gate_update(ull a0, ull a1, float& c,
                                            float* __restrict__ dst)
{
    unsigned i0, i1, i2, i3;
    asm("mov.b64 {%0,%1}, %2;" : "=r"(i0), "=r"(i1) : "l"(a0));
    asm("mov.b64 {%0,%1}, %2;" : "=r"(i2), "=r"(i3) : "l"(a1));
    float gi = __uint_as_float(i0), gf = __uint_as_float(i1);
    float gg = __uint_as_float(i2), go = __uint_as_float(i3);
    c = fsig(gf)*c + fsig(gi)*ftanh_acc(gg);
    float hn = fsig(go)*ftanh_acc(c);
    *reinterpret_cast<float2*>(dst) = make_float2(hn, hn);
}

__global__ void __launch_bounds__(NT, 1)
lstm_seq_kernel(const float* __restrict__ input,
                const float* __restrict__ Wih1, const float* __restrict__ Whh1,
                const float* __restrict__ bih1, const float* __restrict__ bhh1,
                const float* __restrict__ Wih2, const float* __restrict__ Whh2,
                const float* __restrict__ bih2, const float* __restrict__ bhh2,
                const float* __restrict__ Wl,   const float* __restrict__ bl,
                float* __restrict__ out)
{
    extern __shared__ __align__(16) float sm[];
    const int tid = threadIdx.x;
    const int b0  = blockIdx.x * BB;

    // ------- one-time prep: transposed + gate-interleaved weights -------
    // col j = 4u + g  <->  original row = g*H + u   (valid when u < 51)
    for (int idx = tid; idx < SZ_W1T; idx += NT) {
        int k = idx / GP, j = idx % GP;
        int u = j >> 2, g = j & 3;
        float v = 0.0f;
        if (u < H && k < H) v = Whh1[(g*H + u)*H + k];
        sm[OFF_W1T + idx] = v;
    }
    // layer2 K layout: slots 0..50 = h1 (Wih2), 51 = pad, 52..102 = h2 (Whh2), 103 = pad
    for (int idx = tid; idx < SZ_W2T; idx += NT) {
        int k = idx / GP, j = idx % GP;
        int u = j >> 2, g = j & 3;
        float v = 0.0f;
        if (u < H) {
            int row = g*H + u;
            if (k < H)                    v = Wih2[row*H + k];
            else if (k >= 52 && k < 103)  v = Whh2[row*H + (k - 52)];
        }
        sm[OFF_W2T + idx] = v;
    }
    for (int j = tid; j < GP; j += NT) {
        int u = j >> 2, g = j & 3;
        float wx = 0.f, v1 = 0.f, v2 = 0.f;
        if (u < H) {
            int row = g*H + u;
            wx = Wih1[row];
            v1 = bih1[row] + bhh1[row];
            v2 = bih2[row] + bhh2[row];
        }
        sm[OFF_WX + j] = wx;
        sm[OFF_B1 + j] = v1;
        sm[OFF_B2 + j] = v2;
    }
    if (tid < 64) sm[OFF_WL + tid] = (tid < H) ? Wl[tid] : 0.0f;
    for (int idx = tid; idx < BB*TSEQ; idx += NT) {
        int b = idx >> 9, t = idx & 511;
        sm[OFF_IN + b*INROW + t] = input[b0*TSEQ + idx];
    }
    for (int idx = tid; idx < 2*SZ_HBUF; idx += NT) sm[OFF_HD + idx] = 0.0f;
    if (tid < 8)  sm[OFF_OUT + tid] = 0.0f;
    if (tid == 0) sm[OFF_BL] = bl[0];
    __syncthreads();

    const int wid  = tid >> 5, lane = tid & 31;
    const int b    = tid & 7;          // batch
    const int u    = tid >> 3;         // unit (0..51; 51 = pad unit)
    const int j0   = 4*u;

    // loop-invariant per-thread weight/bias registers
    const ulonglong2 wxv = *reinterpret_cast<const ulonglong2*>(sm + OFF_WX + j0);
    const ulonglong2 b1v = *reinterpret_cast<const ulonglong2*>(sm + OFF_B1 + j0);
    const ulonglong2 b2v = *reinterpret_cast<const ulonglong2*>(sm + OFF_B2 + j0);

    float* bufA = sm + OFF_HD;             // holds h_prev this step
    float* bufB = sm + OFF_HD + SZ_HBUF;   // receives h_new this step
    float c1 = 0.f, c2 = 0.f;

    const float* W1T = sm + OFF_W1T;
    const float* W2T = sm + OFF_W2T;
    const float* xin = sm + OFF_IN + b*INROW;

    for (int t = 0; t < TTOT; ++t) {
        // ---- phase A: layer1 matvec + cell update (no intermediate buffer) ----
        {
            float x = (t < TSEQ) ? xin[t] : sm[OFF_OUT + b];
            ull xx = dup2(x);
            ull a0 = ffma2(wxv.x, xx, b1v.x);
            ull a1 = ffma2(wxv.y, xx, b1v.y);
            mv<26>(W1T, bufA + b*HROW, a0, a1, j0);          // h1_prev (slots 0..51)
            gate_update(a0, a1, c1, bufB + b*HROW + 2*u);    // h1_new -> bufB slot u
        }
        __syncthreads();

        // ---- phase B: layer2 matvec + cell update ----
        {
            ull a0 = b2v.x, a1 = b2v.y;
            mv<26>(W2T,          bufB + b*HROW,       a0, a1, j0);  // h1_new
            mv<26>(W2T + 52*GP,  bufA + b*HROW + 104, a0, a1, j0);  // h2_prev (slots 52..103)
            gate_update(a0, a1, c2, bufB + b*HROW + 104 + 2*u);     // h2_new -> bufB slot 52+u
        }
        __syncthreads();

        // ---- output: warps 0-7, batch = wid; reads only bufB h2 region ----
        if (wid < 8) {
            const float* h2p = bufB + wid*HROW + 104;
            float p = h2p[2*lane] * sm[OFF_WL + lane];
            if (lane + 32 < H)
                p += h2p[2*(lane + 32)] * sm[OFF_WL + lane + 32];
            #pragma unroll
            for (int o = 16; o > 0; o >>= 1)
                p += __shfl_xor_sync(0xffffffffu, p, o);
            if (lane == 0) {
                float ov = p + sm[OFF_BL];
                out[(b0 + wid)*TTOT + t] = ov;
                sm[OFF_OUT + wid] = ov;       // consumed only when t+1 >= TSEQ
            }
        }
        if (t >= TSEQ - 1) __syncthreads();   // protect OFF_OUT in future phase

        float* tmp = bufA; bufA = bufB; bufB = tmp;
    }
}

extern "C" void kernel_launch(void* const* d_in, const int* in_sizes, int n_in,
                              void* d_out, int out_size)
{
    (void)n_in; (void)out_size;
    cudaFuncSetAttribute(lstm_seq_kernel,
                         cudaFuncAttributeMaxDynamicSharedMemorySize, SMEM_BYTES);
    int nblocks = in_sizes[0] / (TSEQ * BB);   // B / 8 = 128
    lstm_seq_kernel<<<nblocks, NT, SMEM_BYTES>>>(
        (const float*)d_in[0],  (const float*)d_in[1], (const float*)d_in[2],
        (const float*)d_in[3],  (const float*)d_in[4], (const float*)d_in[5],
        (const float*)d_in[6],  (const float*)d_in[7], (const float*)d_in[8],
        (const float*)d_in[9],  (const float*)d_in[10],
        (float*)d_out);
}

// round 7
// speedup vs baseline: 1.3657x; 1.3657x over previous
#include <cuda_runtime.h>
#include <cstdint>

typedef unsigned long long ull;

#define H     51
#define G4    (4*H)       // 204 real gate cols (interleaved: col = 4h+gate)
#define GP    256         // padded gate cols
#define GROW  260         // g row stride (floats)
#define HROW  212         // dup h row stride: 2*104=208 -> 212
#define BB    8           // batch per block
#define TSEQ  512
#define FUT   64
#define TTOT  (TSEQ + FUT)
#define NT    384         // 12 warps: 2 j-slices x 6 k-splits
#define NKS   6           // split-K factor

// ---- smem layout (float offsets) ----
#define OFF_W1T  0
#define SZ_W1T   (52*GP)                  // 13312
#define OFF_W2T  (OFF_W1T + SZ_W1T)
#define SZ_W2T   (104*GP)                 // 26624
#define OFF_WX   (OFF_W2T + SZ_W2T)       // 39936
#define OFF_B1   (OFF_WX + GP)
#define OFF_B2   (OFF_B1 + GP)
#define OFF_WL   (OFF_B2 + GP)
#define OFF_HD   (OFF_WL + 64)
#define SZ_HD    (BB*HROW)                // 1696
#define OFF_G    (OFF_HD + SZ_HD)
#define SZ_G     (BB*GROW)                // 2080 per split buffer
#define OFF_OUT  (OFF_G + NKS*SZ_G)
#define OFF_BL   (OFF_OUT + 8)
#define SMEM_FLOATS (OFF_BL + 4)          // 54956 -> 219824 B
#define SMEM_BYTES  (SMEM_FLOATS * 4)

__device__ __forceinline__ ull ffma2(ull a, ull b, ull c) {
    ull d;
    asm("fma.rn.f32x2 %0, %1, %2, %3;" : "=l"(d) : "l"(a), "l"(b), "l"(c));
    return d;
}

__device__ __forceinline__ ull dup2(float v) {
    ull r;
    unsigned u = __float_as_uint(v);
    asm("mov.b64 %0, {%1, %2};" : "=l"(r) : "r"(u), "r"(u));
    return r;
}

__device__ __forceinline__ float fsig(float x) {
    float e = __expf(-x);
    return __fdividef(1.0f, 1.0f + e);
}

__device__ __forceinline__ float ftanh_acc(float x) {
    float a = fabsf(x);
    float e = __expf(-2.0f * a);           // <= 1, no overflow
    float r = __fdividef(1.0f - e, 1.0f + e);
    return copysignf(r, x);
}

// Partial matvec over NPAIR k-pairs, 4 gate-cols per lane, 8 batches.
// Per pair: 2 weight LDS.128 (512B unique) + 8 dup-h broadcast LDS.128 ->
// 32 FFMA2. 16 independent accumulator chains (ILP-safe, R3-proven).
template<int NPAIR>
__device__ __forceinline__ void matvec(const float* __restrict__ WT,
                                       const float* __restrict__ hd,
                                       ull acc0[8], ull acc1[8], int j0)
{
    #pragma unroll
    for (int kp = 0; kp < NPAIR; ++kp) {
        ulonglong2 w0 = *reinterpret_cast<const ulonglong2*>(WT + (2*kp  )*GP + j0);
        ulonglong2 w1 = *reinterpret_cast<const ulonglong2*>(WT + (2*kp+1)*GP + j0);
        #pragma unroll
        for (int b = 0; b < 8; ++b) {
            ulonglong2 hv = *reinterpret_cast<const ulonglong2*>(hd + b*HROW + 4*kp);
            acc0[b] = ffma2(w0.x, hv.x, acc0[b]);
            acc1[b] = ffma2(w0.y, hv.x, acc1[b]);
            acc0[b] = ffma2(w1.x, hv.y, acc0[b]);
            acc1[b] = ffma2(w1.y, hv.y, acc1[b]);
        }
    }
}

__device__ __forceinline__ void store_acc(float* __restrict__ gout,
                                          ull acc0[8], ull acc1[8], int j0)
{
    #pragma unroll
    for (int b = 0; b < 8; ++b)
        *reinterpret_cast<ulonglong2*>(gout + b*GROW + j0) =
            make_ulonglong2(acc0[b], acc1[b]);
}

// gate nonlinearity: 408 (b,h) tasks over 384 threads (2 iters, 2nd sparse);
// interleaved layout -> one LDS.128 per split buffer gives (i,f,g,o) of unit h.
__device__ __forceinline__ void gates(const float* __restrict__ g,
                                      float* __restrict__ hd,
                                      float creg[2], int hoff, int tid)
{
    #pragma unroll
    for (int i = 0; i < 2; ++i) {
        int tt = tid + i*NT;
        if (tt < BB*H) {
            int b = tt & 7, h = tt >> 3;
            const float* gp = g + b*GROW + 4*h;
            float gi = 0.f, gf = 0.f, gg = 0.f, go = 0.f;
            #pragma unroll
            for (int s = 0; s < NKS; ++s) {
                float4 v = *reinterpret_cast<const float4*>(gp + s*SZ_G);
                gi += v.x; gf += v.y; gg += v.z; go += v.w;
            }
            float c  = fsig(gf)*creg[i] + fsig(gi)*ftanh_acc(gg);
            float hn = fsig(go)*ftanh_acc(c);
            creg[i] = c;
            *reinterpret_cast<float2*>(hd + b*HROW + 2*(hoff + h)) = make_float2(hn, hn);
        }
    }
}

__global__ void __launch_bounds__(NT, 1)
lstm_seq_kernel(const float* __restrict__ input,
                const float* __restrict__ Wih1, const float* __restrict__ Whh1,
                const float* __restrict__ bih1, const float* __restrict__ bhh1,
                const float* __restrict__ Wih2, const float* __restrict__ Whh2,
                const float* __restrict__ bih2, const float* __restrict__ bhh2,
                const float* __restrict__ Wl,   const float* __restrict__ bl,
                float* __restrict__ out)
{
    extern __shared__ __align__(16) float sm[];
    const int tid = threadIdx.x;
    const int b0  = blockIdx.x * BB;

    // ------- one-time prep: transposed + gate-interleaved weights -------
    // interleaved col j = 4h+g  <->  original row = g*H + h
    for (int idx = tid; idx < SZ_W1T; idx += NT) {
        int k = idx >> 8, j = idx & 255;
        float v = 0.0f;
        if (j < G4 && k < H) {
            int row = (j & 3)*H + (j >> 2);
            v = Whh1[row*H + k];
        }
        sm[OFF_W1T + idx] = v;
    }
    for (int idx = tid; idx < SZ_W2T; idx += NT) {
        int k = idx >> 8, j = idx & 255;
        float v = 0.0f;
        if (j < G4) {
            int row = (j & 3)*H + (j >> 2);
            if (k < H)        v = Wih2[row*H + k];
            else if (k < 2*H) v = Whh2[row*H + (k - H)];
        }
        sm[OFF_W2T + idx] = v;
    }
    for (int j = tid; j < GP; j += NT) {
        float wx = 0.f, v1 = 0.f, v2 = 0.f;
        if (j < G4) {
            int row = (j & 3)*H + (j >> 2);
            wx = Wih1[row];
            v1 = bih1[row] + bhh1[row];
            v2 = bih2[row] + bhh2[row];
        }
        sm[OFF_WX + j] = wx;
        sm[OFF_B1 + j] = v1;
        sm[OFF_B2 + j] = v2;
    }
    if (tid < 64) sm[OFF_WL + tid] = (tid < H) ? Wl[tid] : 0.0f;
    for (int idx = tid; idx < SZ_HD; idx += NT) sm[OFF_HD + idx] = 0.0f;
    for (int idx = tid; idx < NKS*SZ_G; idx += NT) sm[OFF_G + idx] = 0.0f;
    if (tid < 8)   sm[OFF_OUT + tid] = 0.0f;
    if (tid == 0)  sm[OFF_BL] = bl[0];
    __syncthreads();

    float c1r[2] = {0.f, 0.f};
    float c2r[2] = {0.f, 0.f};

    const int wid  = tid >> 5, lane = tid & 31;
    const int js   = wid & 1;                // j-slice (2 x 128 cols)
    const int kh   = wid >> 1;               // k-split group (0..5)
    const int j0   = js*128 + lane*4;        // 4 cols = one unit's (i,f,g,o)
    float* gout = sm + OFF_G + kh*SZ_G;

    // layer1: 26 k-pairs split {5,5,4,4,4,4}; layer2: 52 pairs {9,9,9,9,8,8}
    const int s1 = (kh < 2) ? 5*kh : 10 + 4*(kh - 2);
    const int s2 = (kh < 4) ? 9*kh : 36 + 8*(kh - 4);
    const float* W1T = sm + OFF_W1T + s1*2*GP;
    const float* W2T = sm + OFF_W2T + s2*2*GP;
    const float* hd1 = sm + OFF_HD + s1*4;
    const float* hd2 = sm + OFF_HD + s2*4;
    float* hd = sm + OFF_HD;

    // x prefetch (kh==0 warps): lane b<8 holds input[(b0+b)*T + t]
    float xcur = 0.f;
    if (kh == 0 && lane < 8) xcur = input[(b0 + lane)*TSEQ];

    for (int t = 0; t < TTOT; ++t) {
        // ---- matvec layer 1 (partial over this warp's k-pairs) ----
        {
            ull acc0[8], acc1[8];
            if (kh == 0) {
                ulonglong2 bv  = *reinterpret_cast<const ulonglong2*>(sm + OFF_B1 + j0);
                ulonglong2 wxv = *reinterpret_cast<const ulonglong2*>(sm + OFF_WX + j0);
                #pragma unroll
                for (int b = 0; b < 8; ++b) {
                    float x = (t < TSEQ) ? __shfl_sync(0xffffffffu, xcur, b)
                                         : sm[OFF_OUT + b];
                    ull xx = dup2(x);
                    acc0[b] = ffma2(wxv.x, xx, bv.x);
                    acc1[b] = ffma2(wxv.y, xx, bv.y);
                }
                if (t + 1 < TSEQ && lane < 8)
                    xcur = input[(b0 + lane)*TSEQ + (t + 1)];
            } else {
                #pragma unroll
                for (int b = 0; b < 8; ++b) { acc0[b] = 0ull; acc1[b] = 0ull; }
            }
            if (kh < 2) matvec<5>(W1T, hd1, acc0, acc1, j0);
            else        matvec<4>(W1T, hd1, acc0, acc1, j0);
            store_acc(gout, acc0, acc1, j0);
        }
        __syncthreads();

        gates(sm + OFF_G, hd, c1r, 0, tid);     // h1 -> hd dup[0..2H)
        __syncthreads();

        // ---- matvec layer 2 (partial over this warp's k-pairs) ----
        {
            ull acc0[8], acc1[8];
            if (kh == 0) {
                ulonglong2 bv = *reinterpret_cast<const ulonglong2*>(sm + OFF_B2 + j0);
                #pragma unroll
                for (int b = 0; b < 8; ++b) { acc0[b] = bv.x; acc1[b] = bv.y; }
            } else {
                #pragma unroll
                for (int b = 0; b < 8; ++b) { acc0[b] = 0ull; acc1[b] = 0ull; }
            }
            if (kh < 4) matvec<9>(W2T, hd2, acc0, acc1, j0);
            else        matvec<8>(W2T, hd2, acc0, acc1, j0);
            store_acc(gout, acc0, acc1, j0);
        }
        __syncthreads();

        gates(sm + OFF_G, hd, c2r, H, tid);     // h2 -> hd dup[2H..4H)
        __syncthreads();

        // ---- output: warps 0-7, batch = wid; reads only h2 region ----
        if (wid < 8) {
            const float* h2p = hd + wid*HROW + 2*H;
            float p = h2p[2*lane] * sm[OFF_WL + lane];
            if (lane + 32 < H)
                p += h2p[2*(lane + 32)] * sm[OFF_WL + lane + 32];
            #pragma unroll
            for (int o = 16; o > 0; o >>= 1)
                p += __shfl_xor_sync(0xffffffffu, p, o);
            if (lane == 0) {
                float ov = p + sm[OFF_BL];
                out[(b0 + wid)*TTOT + t] = ov;
                sm[OFF_OUT + wid] = ov;       // consumed only when t+1 >= TSEQ
            }
        }
        if (t >= TSEQ - 1) __syncthreads();   // protect OFF_OUT in future phase
    }
}

extern "C" void kernel_launch(void* const* d_in, const int* in_sizes, int n_in,
                              void* d_out, int out_size)
{
    (void)n_in; (void)out_size;
    cudaFuncSetAttribute(lstm_seq_kernel,
                         cudaFuncAttributeMaxDynamicSharedMemorySize, SMEM_BYTES);
    int nblocks = in_sizes[0] / (TSEQ * BB);   // B / 8 = 128
    lstm_seq_kernel<<<nblocks, NT, SMEM_BYTES>>>(
        (const float*)d_in[0],  (const float*)d_in[1], (const float*)d_in[2],
        (const float*)d_in[3],  (const float*)d_in[4], (const float*)d_in[5],
        (const float*)d_in[6],  (const float*)d_in[7], (const float*)d_in[8],
        (const float*)d_in[9],  (const float*)d_in[10],
        (float*)d_out);
}